// round 15
// baseline (speedup 1.0000x reference)
#include <cuda_runtime.h>
#include <cstdint>
#include <cstddef>

// Problem constants
#define BB 4
#define SS 4096
#define HH 16
#define DD 64
#define GM 16384   // B*S
#define GN 1024    // H*D == OUT
#define GK 1024    // IN == H*D

// Intermediate buffers (allocation-free rule: device globals)
__device__ float g_xp[(size_t)GM * GN];  // input projection  [B,S,H*D]
__device__ float g_y [(size_t)GM * GN];  // scan outputs      [B,S,H*D]

// ---------------------------------------------------------------------------
// tf32 helpers
// ---------------------------------------------------------------------------
__device__ __forceinline__ uint32_t f2tf32(float f) {
    uint32_t u;
    asm("cvt.rna.tf32.f32 %0, %1;" : "=r"(u) : "f"(f));
    return u;
}

__device__ __forceinline__ void mma_tf32(float c[4], const uint32_t a[4], const uint32_t b[2]) {
    asm volatile(
        "mma.sync.aligned.m16n8k8.row.col.f32.tf32.tf32.f32 "
        "{%0,%1,%2,%3}, {%4,%5,%6,%7}, {%8,%9}, {%0,%1,%2,%3};"
        : "+f"(c[0]), "+f"(c[1]), "+f"(c[2]), "+f"(c[3])
        : "r"(a[0]), "r"(a[1]), "r"(a[2]), "r"(a[3]), "r"(b[0]), "r"(b[1]));
}

// ---------------------------------------------------------------------------
// GEMM: C[M,N] = A[M,K] * B[N,K]^T   (unchanged — 265us each)
// ---------------------------------------------------------------------------
__global__ __launch_bounds__(256) void gemm_tf32(
    const float* __restrict__ A, const float* __restrict__ B, float* __restrict__ C)
{
    __shared__ uint4 As4[128 * 8];
    __shared__ uint4 Bs4[128 * 8];

    const int tid  = threadIdx.x;
    const int warp = tid >> 5;
    const int lane = tid & 31;
    const int wm   = warp >> 1;      // 0..3
    const int wn   = warp & 1;       // 0..1
    const int g    = lane >> 2;      // group 0..7
    const int t4   = lane & 3;       // thread-in-group
    const int lr   = tid >> 3;       // staging row 0..31
    const int lc4  = tid & 7;        // staging float4 col 0..7
    const int bm   = blockIdx.y * 128;
    const int bn   = blockIdx.x * 128;

    const float4* Ag = reinterpret_cast<const float4*>(A) + (size_t)(bm + lr) * (GK / 4) + lc4;
    const float4* Bg = reinterpret_cast<const float4*>(B) + (size_t)(bn + lr) * (GK / 4) + lc4;
    const int sw = lc4 ^ (lr & 7);

    float acc[2][8][4];
#pragma unroll
    for (int mi = 0; mi < 2; ++mi)
#pragma unroll
        for (int ni = 0; ni < 8; ++ni)
#pragma unroll
            for (int r = 0; r < 4; ++r) acc[mi][ni][r] = 0.f;

    // prologue: stage K-tile 0
    float4 pa[4], pb[4];
#pragma unroll
    for (int i = 0; i < 4; ++i) {
        pa[i] = Ag[(size_t)i * 32 * (GK / 4)];
        pb[i] = Bg[(size_t)i * 32 * (GK / 4)];
    }

    const uint32_t* As = reinterpret_cast<const uint32_t*>(As4);
    const uint32_t* Bs = reinterpret_cast<const uint32_t*>(Bs4);
    const uint32_t* Abase = As + (wm * 32 + g) * 32 + t4;
    const uint32_t* Bbase = Bs + (wn * 64 + g) * 32 + t4;

    for (int kt = 0; kt < GK / 32; ++kt) {
        __syncthreads();   // previous compute finished reading smem
#pragma unroll
        for (int i = 0; i < 4; ++i) {
            As4[(lr + 32 * i) * 8 + sw] =
                make_uint4(f2tf32(pa[i].x), f2tf32(pa[i].y), f2tf32(pa[i].z), f2tf32(pa[i].w));
            Bs4[(lr + 32 * i) * 8 + sw] =
                make_uint4(f2tf32(pb[i].x), f2tf32(pb[i].y), f2tf32(pb[i].z), f2tf32(pb[i].w));
        }
        __syncthreads();   // smem tile ready

        if (kt + 1 < GK / 32) {        // prefetch next tile (overlaps compute)
#pragma unroll
            for (int i = 0; i < 4; ++i) {
                pa[i] = Ag[(size_t)(kt + 1) * 8 + (size_t)i * 32 * (GK / 4)];
                pb[i] = Bg[(size_t)(kt + 1) * 8 + (size_t)i * 32 * (GK / 4)];
            }
        }

#pragma unroll
        for (int j = 0; j < 4; ++j) {          // 4 k8-steps per K-tile
            const int x0 = ((2 * j) ^ g) * 4;  // swizzled scalar offset, first half
            uint32_t af[2][4];
#pragma unroll
            for (int mi = 0; mi < 2; ++mi) {
                const uint32_t* p = Abase + mi * 16 * 32;
                af[mi][0] = p[x0];
                af[mi][1] = p[8 * 32 + x0];
                af[mi][2] = p[x0 ^ 4];
                af[mi][3] = p[8 * 32 + (x0 ^ 4)];
            }
#pragma unroll
            for (int ni = 0; ni < 8; ++ni) {
                const uint32_t* p = Bbase + ni * 8 * 32;
                uint32_t bf[2] = { p[x0], p[x0 ^ 4] };
                mma_tf32(acc[0][ni], af[0], bf);
                mma_tf32(acc[1][ni], af[1], bf);
            }
        }
    }

    // epilogue: direct float2 stores
#pragma unroll
    for (int mi = 0; mi < 2; ++mi) {
        const int row = bm + wm * 32 + mi * 16 + g;
#pragma unroll
        for (int ni = 0; ni < 8; ++ni) {
            const int col = bn + wn * 64 + ni * 8 + t4 * 2;
            *reinterpret_cast<float2*>(C + (size_t)row * GN + col) =
                make_float2(acc[mi][ni][0], acc[mi][ni][1]);
            *reinterpret_cast<float2*>(C + (size_t)(row + 8) * GN + col) =
                make_float2(acc[mi][ni][2], acc[mi][ni][3]);
        }
    }
}

// ---------------------------------------------------------------------------
// packed f32x2 helpers (sm_103a FFMA2 — only reachable via PTX)
// ---------------------------------------------------------------------------
__device__ __forceinline__ void ffma2(uint64_t& c, uint64_t a, uint64_t b) {
    asm("fma.rn.f32x2 %0, %1, %2, %0;" : "+l"(c) : "l"(a), "l"(b));
}
__device__ __forceinline__ void fadd2(uint64_t& c, uint64_t a) {
    asm("add.rn.f32x2 %0, %0, %1;" : "+l"(c) : "l"(a));
}
__device__ __forceinline__ float2 unpk(uint64_t v) {
    float2 r;
    asm("mov.b64 {%0,%1}, %2;" : "=f"(r.x), "=f"(r.y) : "l"(v));
    return r;
}

// fast tanh: 1 - 2/(exp(2z)+1).  ~45cyc, correct saturation, ~1e-7 error.
__device__ __forceinline__ float fast_tanh(float z) {
    float ez = __expf(z + z);
    return 1.0f - __fdividef(2.0f, ez + 1.0f);
}

// ---------------------------------------------------------------------------
// k-split scan: one block of 4 WARPS per (b,h).
//   Warp w computes partial dot-products for ALL 64 elements over its
//   k-quarter [16w,16w+16): 8 FFMA2 per thread (2 els x 16 k) -- 4x the issue
//   bandwidth of the R14 single-warp version (which was issue-bound ~400cyc).
//   Partials exchanged via double-buffered smem pb[2][4][64]; ONE
//   __syncthreads per step.  After the bar every warp REDUNDANTLY computes
//   sum+tanh for its 2 elements (bitwise identical in all warps) and writes
//   its own private h-state copy hs[w] -> next step's reads are warp-local,
//   ordered by __syncwarp only.  bias+x folded into warp 0's partial
//   (pre-bar), so warps 1-3 never read x.  pb double-buffering is safe: a
//   warp can only reuse a parity after the next step's bar, which requires
//   all other warps to have finished reading it.
// ---------------------------------------------------------------------------
__global__ void __launch_bounds__(128) rnn_scan(
    const float* __restrict__ xp, const float* __restrict__ h0,
    const float* __restrict__ Wst, const float* __restrict__ bias,
    float* __restrict__ y)
{
    const int b    = blockIdx.x >> 4;
    const int h    = blockIdx.x & 15;
    const int tid  = threadIdx.x;
    const int w    = tid >> 5;
    const int lane = tid & 31;
    const int e0   = 2 * lane;

    __shared__ __align__(16) float hs[4][2][64];   // per-warp private, double-buffered
    __shared__ __align__(16) float pb[2][4][64];   // partials, double-buffered

    // weights: rows e0, e0+1, k-slice [16w, 16w+16), packed as f32x2 pairs
    uint64_t wk0[8], wk1[8];
    {
        const uint64_t* r0 = reinterpret_cast<const uint64_t*>(
            Wst + ((size_t)(h * 64 + e0)) * 64 + 16 * w);
        const uint64_t* r1 = reinterpret_cast<const uint64_t*>(
            Wst + ((size_t)(h * 64 + e0 + 1)) * 64 + 16 * w);
#pragma unroll
        for (int j = 0; j < 8; ++j) { wk0[j] = r0[j]; wk1[j] = r1[j]; }
    }
    const float2 be = *reinterpret_cast<const float2*>(bias + h * 64 + e0);

    // init private h-state copy
    reinterpret_cast<float2*>(hs[w][0])[lane] =
        reinterpret_cast<const float2*>(h0 + (size_t)(b * HH + h) * 64)[lane];

    const float2* xb2 = reinterpret_cast<const float2*>(
        xp + (size_t)b * SS * 1024 + h * 64) + lane;     // step stride = 512 float2
    float2* yb2 = reinterpret_cast<float2*>(
        y + (size_t)b * SS * 1024 + h * 64) + lane;

    // depth-8 prefetch ring — warp 0 only (bias+x folded into its partial)
    float2 xr[8];
#pragma unroll
    for (int i = 0; i < 8; ++i)
        xr[i] = (w == 0) ? xb2[(size_t)i * 512] : make_float2(0.f, 0.f);

    __syncthreads();

    int cur = 0;
    for (int s = 0; s < SS; s += 8) {
#pragma unroll
        for (int i = 0; i < 8; ++i) {
            const int st = s + i;

            // issue next prefetch first (warp 0, independent of compute)
            float2 xn = make_float2(0.f, 0.f);
            if (w == 0 && st + 8 < SS) xn = xb2[(size_t)(st + 8) * 512];

            // partial dot: 2 els x 16 k = 8 FFMA2, broadcast LDS.128 of h slice
            const ulonglong2* hv = reinterpret_cast<const ulonglong2*>(
                &hs[w][cur][16 * w]);
            uint64_t a0 = 0, b0 = 0, a1 = 0, b1 = 0;
#pragma unroll
            for (int k = 0; k < 4; ++k) {
                ulonglong2 q = hv[k];
                ffma2(a0, wk0[2 * k],     q.x);
                ffma2(b0, wk0[2 * k + 1], q.y);
                ffma2(a1, wk1[2 * k],     q.x);
                ffma2(b1, wk1[2 * k + 1], q.y);
            }
            fadd2(a0, b0); fadd2(a1, b1);
            float2 u0 = unpk(a0), u1 = unpk(a1);
            float p0 = u0.x + u0.y;
            float p1 = u1.x + u1.y;
            if (w == 0) { p0 += be.x + xr[i].x; p1 += be.y + xr[i].y; }
            *reinterpret_cast<float2*>(&pb[cur][w][e0]) = make_float2(p0, p1);

            __syncthreads();   // the ONLY block barrier per step

            // sum 4 partials (packed tree, identical order in all warps)
            uint64_t q0 = *reinterpret_cast<const uint64_t*>(&pb[cur][0][e0]);
            uint64_t q1 = *reinterpret_cast<const uint64_t*>(&pb[cur][1][e0]);
            uint64_t q2 = *reinterpret_cast<const uint64_t*>(&pb[cur][2][e0]);
            uint64_t q3 = *reinterpret_cast<const uint64_t*>(&pb[cur][3][e0]);
            fadd2(q0, q1); fadd2(q2, q3); fadd2(q0, q2);
            float2 sv = unpk(q0);

            const float2 hn = make_float2(fast_tanh(sv.x), fast_tanh(sv.y));

            *reinterpret_cast<float2*>(&hs[w][cur ^ 1][e0]) = hn;  // private copy
            if (w == 0) yb2[(size_t)st * 512] = hn;                // stream output
            __syncwarp();
            cur ^= 1;

            if (w == 0) xr[i] = xn;
        }
    }
}

// ---------------------------------------------------------------------------
// Launch
// ---------------------------------------------------------------------------
extern "C" void kernel_launch(void* const* d_in, const int* in_sizes, int n_in,
                              void* d_out, int out_size)
{
    const float* x     = (const float*)d_in[0];  // [B,S,IN]
    const float* h0    = (const float*)d_in[1];  // [B,H,D]
    const float* w_in  = (const float*)d_in[2];  // [H*D, IN]
    const float* Wst   = (const float*)d_in[3];  // [H,D,D]
    const float* bias  = (const float*)d_in[4];  // [H,D]
    const float* w_out = (const float*)d_in[5];  // [OUT, H*D]
    float* out = (float*)d_out;                  // [B,S,OUT]

    float *xp = nullptr, *yy = nullptr;
    cudaGetSymbolAddress((void**)&xp, g_xp);
    cudaGetSymbolAddress((void**)&yy, g_y);

    dim3 grid(GN / 128, GM / 128);   // (8, 128)
    gemm_tf32<<<grid, 256>>>(x, w_in, xp);              // input projection
    rnn_scan<<<BB * HH, 128>>>(xp, h0, Wst, bias, yy);  // sequential recurrence
    gemm_tf32<<<grid, 256>>>(yy, w_out, out);           // output projection
}

// round 16
// speedup vs baseline: 2.2630x; 2.2630x over previous
#include <cuda_runtime.h>
#include <cstdint>
#include <cstddef>

// Problem constants
#define BB 4
#define SS 4096
#define HH 16
#define DD 64
#define GM 16384   // B*S
#define GN 1024    // H*D == OUT
#define GK 1024    // IN == H*D

#define NC 8            // pipeline chunks
#define CS (SS / NC)    // 512 steps per chunk
#define TPB (CS / 128)  // M-tiles per batch per chunk = 4

// Intermediate buffers (allocation-free rule: device globals)
__device__ float g_xp[(size_t)GM * GN];   // input projection  [B,S,H*D]
__device__ float g_y [(size_t)GM * GN];   // scan outputs      [B,S,H*D]
__device__ float g_h [BB * HH * DD];      // carried h-state between chunks

// ---------------------------------------------------------------------------
// tf32 helpers
// ---------------------------------------------------------------------------
__device__ __forceinline__ uint32_t f2tf32(float f) {
    uint32_t u;
    asm("cvt.rna.tf32.f32 %0, %1;" : "=r"(u) : "f"(f));
    return u;
}

__device__ __forceinline__ void mma_tf32(float c[4], const uint32_t a[4], const uint32_t b[2]) {
    asm volatile(
        "mma.sync.aligned.m16n8k8.row.col.f32.tf32.tf32.f32 "
        "{%0,%1,%2,%3}, {%4,%5,%6,%7}, {%8,%9}, {%0,%1,%2,%3};"
        : "+f"(c[0]), "+f"(c[1]), "+f"(c[2]), "+f"(c[3])
        : "r"(a[0]), "r"(a[1]), "r"(a[2]), "r"(a[3]), "r"(b[0]), "r"(b[1]));
}

// ---------------------------------------------------------------------------
// Chunked GEMM: processes M-rows {b*SS + s0 + tile*128 | b in [0,4), tile in
// [0,TPB)} of C[M,N] = A[M,K] * B[N,K]^T.  grid = (GN/128, BB*TPB).
// Inner structure identical to the R12 gemm (265us full / ~1 wave per chunk).
// ---------------------------------------------------------------------------
__global__ __launch_bounds__(256) void gemm_tf32_chunk(
    const float* __restrict__ A, const float* __restrict__ B, float* __restrict__ C,
    int s0)
{
    __shared__ uint4 As4[128 * 8];
    __shared__ uint4 Bs4[128 * 8];

    const int tid  = threadIdx.x;
    const int warp = tid >> 5;
    const int lane = tid & 31;
    const int wm   = warp >> 1;      // 0..3
    const int wn   = warp & 1;       // 0..1
    const int g    = lane >> 2;      // group 0..7
    const int t4   = lane & 3;       // thread-in-group
    const int lr   = tid >> 3;       // staging row 0..31
    const int lc4  = tid & 7;        // staging float4 col 0..7

    const int bty  = blockIdx.y;
    const int bm   = (bty >> 2) * SS + s0 + (bty & 3) * 128;  // TPB==4
    const int bn   = blockIdx.x * 128;

    const float4* Ag = reinterpret_cast<const float4*>(A) + (size_t)(bm + lr) * (GK / 4) + lc4;
    const float4* Bg = reinterpret_cast<const float4*>(B) + (size_t)(bn + lr) * (GK / 4) + lc4;
    const int sw = lc4 ^ (lr & 7);

    float acc[2][8][4];
#pragma unroll
    for (int mi = 0; mi < 2; ++mi)
#pragma unroll
        for (int ni = 0; ni < 8; ++ni)
#pragma unroll
            for (int r = 0; r < 4; ++r) acc[mi][ni][r] = 0.f;

    float4 pa[4], pb[4];
#pragma unroll
    for (int i = 0; i < 4; ++i) {
        pa[i] = Ag[(size_t)i * 32 * (GK / 4)];
        pb[i] = Bg[(size_t)i * 32 * (GK / 4)];
    }

    const uint32_t* As = reinterpret_cast<const uint32_t*>(As4);
    const uint32_t* Bs = reinterpret_cast<const uint32_t*>(Bs4);
    const uint32_t* Abase = As + (wm * 32 + g) * 32 + t4;
    const uint32_t* Bbase = Bs + (wn * 64 + g) * 32 + t4;

    for (int kt = 0; kt < GK / 32; ++kt) {
        __syncthreads();
#pragma unroll
        for (int i = 0; i < 4; ++i) {
            As4[(lr + 32 * i) * 8 + sw] =
                make_uint4(f2tf32(pa[i].x), f2tf32(pa[i].y), f2tf32(pa[i].z), f2tf32(pa[i].w));
            Bs4[(lr + 32 * i) * 8 + sw] =
                make_uint4(f2tf32(pb[i].x), f2tf32(pb[i].y), f2tf32(pb[i].z), f2tf32(pb[i].w));
        }
        __syncthreads();

        if (kt + 1 < GK / 32) {
#pragma unroll
            for (int i = 0; i < 4; ++i) {
                pa[i] = Ag[(size_t)(kt + 1) * 8 + (size_t)i * 32 * (GK / 4)];
                pb[i] = Bg[(size_t)(kt + 1) * 8 + (size_t)i * 32 * (GK / 4)];
            }
        }

#pragma unroll
        for (int j = 0; j < 4; ++j) {
            const int x0 = ((2 * j) ^ g) * 4;
            uint32_t af[2][4];
#pragma unroll
            for (int mi = 0; mi < 2; ++mi) {
                const uint32_t* p = Abase + mi * 16 * 32;
                af[mi][0] = p[x0];
                af[mi][1] = p[8 * 32 + x0];
                af[mi][2] = p[x0 ^ 4];
                af[mi][3] = p[8 * 32 + (x0 ^ 4)];
            }
#pragma unroll
            for (int ni = 0; ni < 8; ++ni) {
                const uint32_t* p = Bbase + ni * 8 * 32;
                uint32_t bf[2] = { p[x0], p[x0 ^ 4] };
                mma_tf32(acc[0][ni], af[0], bf);
                mma_tf32(acc[1][ni], af[1], bf);
            }
        }
    }

#pragma unroll
    for (int mi = 0; mi < 2; ++mi) {
        const int row = bm + wm * 32 + mi * 16 + g;
#pragma unroll
        for (int ni = 0; ni < 8; ++ni) {
            const int col = bn + wn * 64 + ni * 8 + t4 * 2;
            *reinterpret_cast<float2*>(C + (size_t)row * GN + col) =
                make_float2(acc[mi][ni][0], acc[mi][ni][1]);
            *reinterpret_cast<float2*>(C + (size_t)(row + 8) * GN + col) =
                make_float2(acc[mi][ni][2], acc[mi][ni][3]);
        }
    }
}

// ---------------------------------------------------------------------------
// packed f32x2 helpers (sm_103a FFMA2 — only reachable via PTX)
// ---------------------------------------------------------------------------
__device__ __forceinline__ void ffma2(uint64_t& c, uint64_t a, uint64_t b) {
    asm("fma.rn.f32x2 %0, %1, %2, %0;" : "+l"(c) : "l"(a), "l"(b));
}
__device__ __forceinline__ void fadd2(uint64_t& c, uint64_t a) {
    asm("add.rn.f32x2 %0, %0, %1;" : "+l"(c) : "l"(a));
}
__device__ __forceinline__ float2 unpk(uint64_t v) {
    float2 r;
    asm("mov.b64 {%0,%1}, %2;" : "=f"(r.x), "=f"(r.y) : "l"(v));
    return r;
}

// fast tanh: 1 - 2/(exp(2z)+1).  ~45cyc, correct saturation, ~1e-7 error.
__device__ __forceinline__ float fast_tanh(float z) {
    float ez = __expf(z + z);
    return 1.0f - __fdividef(2.0f, ez + 1.0f);
}

// ---------------------------------------------------------------------------
// Warp-synchronous scan CHUNK: steps [s0, s0+CS).  Identical inner loop to
// the best (R14) scan — one warp per (b,h), no block barriers.  h-state
// carried across chunk launches in g_h (same stream -> ordered).
// ---------------------------------------------------------------------------
__global__ void __launch_bounds__(32) rnn_scan_chunk(
    const float* __restrict__ xp, const float* __restrict__ h0,
    const float* __restrict__ Wst, const float* __restrict__ bias,
    float* __restrict__ y, int s0)
{
    const int b  = blockIdx.x >> 4;
    const int h  = blockIdx.x & 15;
    const int t  = threadIdx.x;
    const int e0 = 2 * t;

    __shared__ __align__(16) float hs[2][64];

    // weight rows e0, e0+1 packed as f32x2 k-pairs
    uint64_t w0[32], w1[32];
    {
        const uint64_t* p0 = reinterpret_cast<const uint64_t*>(
            Wst + ((size_t)(h * 64 + e0)) * 64);
        const uint64_t* p1 = p0 + 32;
#pragma unroll
        for (int k = 0; k < 32; ++k) { w0[k] = p0[k]; w1[k] = p1[k]; }
    }
    const float2 be = *reinterpret_cast<const float2*>(bias + h * 64 + e0);

    // chunk-initial state: h0 for the first chunk, carried g_h otherwise
    const float* hsrc = (s0 == 0) ? (h0 + (size_t)(b * HH + h) * 64)
                                  : (g_h + (size_t)(b * HH + h) * 64);
    reinterpret_cast<float2*>(hs[0])[t] =
        reinterpret_cast<const float2*>(hsrc)[t];

    const float2* xb2 = reinterpret_cast<const float2*>(
        xp + (size_t)b * SS * 1024 + h * 64) + t;     // step stride = 512 float2
    float2* yb2 = reinterpret_cast<float2*>(
        y + (size_t)b * SS * 1024 + h * 64) + t;

    // depth-8 prefetch ring
    float2 xr[8];
#pragma unroll
    for (int i = 0; i < 8; ++i) xr[i] = xb2[(size_t)(s0 + i) * 512];

    __syncwarp();

    int cur = 0;
    for (int s = s0; s < s0 + CS; s += 8) {
#pragma unroll
        for (int i = 0; i < 8; ++i) {
            const int st = s + i;

            float2 xn = make_float2(0.f, 0.f);
            if (st + 8 < SS) xn = xb2[(size_t)(st + 8) * 512];

            const ulonglong2* hv = reinterpret_cast<const ulonglong2*>(hs[cur]);
            uint64_t a0[4] = {0, 0, 0, 0}, a1[4] = {0, 0, 0, 0};
#pragma unroll
            for (int k = 0; k < 16; ++k) {
                ulonglong2 q = hv[k];
                ffma2(a0[(2 * k) & 3],     w0[2 * k],     q.x);
                ffma2(a0[(2 * k + 1) & 3], w0[2 * k + 1], q.y);
                ffma2(a1[(2 * k) & 3],     w1[2 * k],     q.x);
                ffma2(a1[(2 * k + 1) & 3], w1[2 * k + 1], q.y);
            }
            fadd2(a0[0], a0[1]); fadd2(a0[2], a0[3]); fadd2(a0[0], a0[2]);
            fadd2(a1[0], a1[1]); fadd2(a1[2], a1[3]); fadd2(a1[0], a1[2]);
            float2 v0 = unpk(a0[0]);
            float2 v1 = unpk(a1[0]);

            const float hn0 = fast_tanh((v0.x + v0.y) + be.x + xr[i].x);
            const float hn1 = fast_tanh((v1.x + v1.y) + be.y + xr[i].y);
            const float2 hn = make_float2(hn0, hn1);

            yb2[(size_t)st * 512] = hn;
            *reinterpret_cast<float2*>(&hs[cur ^ 1][e0]) = hn;
            __syncwarp();
            cur ^= 1;

            xr[i] = xn;
        }
    }

    // persist chunk-final state
    reinterpret_cast<float2*>(g_h + (size_t)(b * HH + h) * 64)[t] =
        reinterpret_cast<const float2*>(hs[cur])[t];
}

// ---------------------------------------------------------------------------
// Launch: 3-stage chunked pipeline across 3 streams (fork/join via events —
// capture-legal).  GEMM1 chunks feed the scan; scan chunks feed GEMM2.
// Streams/events created lazily on the first (non-captured) call.
// ---------------------------------------------------------------------------
extern "C" void kernel_launch(void* const* d_in, const int* in_sizes, int n_in,
                              void* d_out, int out_size)
{
    const float* x     = (const float*)d_in[0];  // [B,S,IN]
    const float* h0    = (const float*)d_in[1];  // [B,H,D]
    const float* w_in  = (const float*)d_in[2];  // [H*D, IN]
    const float* Wst   = (const float*)d_in[3];  // [H,D,D]
    const float* bias  = (const float*)d_in[4];  // [H,D]
    const float* w_out = (const float*)d_in[5];  // [OUT, H*D]
    float* out = (float*)d_out;                  // [B,S,OUT]

    float *xp = nullptr, *yy = nullptr;
    cudaGetSymbolAddress((void**)&xp, g_xp);
    cudaGetSymbolAddress((void**)&yy, g_y);

    static cudaStream_t s_scan = nullptr, s_out = nullptr;
    static cudaEvent_t  ev_root = nullptr, ev_done = nullptr;
    static cudaEvent_t  ev_g1[NC], ev_sc[NC];
    if (!s_scan) {
        cudaStreamCreateWithFlags(&s_scan, cudaStreamNonBlocking);
        cudaStreamCreateWithFlags(&s_out,  cudaStreamNonBlocking);
        cudaEventCreateWithFlags(&ev_root, cudaEventDisableTiming);
        cudaEventCreateWithFlags(&ev_done, cudaEventDisableTiming);
        for (int c = 0; c < NC; ++c) {
            cudaEventCreateWithFlags(&ev_g1[c], cudaEventDisableTiming);
            cudaEventCreateWithFlags(&ev_sc[c], cudaEventDisableTiming);
        }
    }

    // fork side streams off the capture (legacy) stream
    cudaEventRecord(ev_root, 0);
    cudaStreamWaitEvent(s_scan, ev_root, 0);
    cudaStreamWaitEvent(s_out,  ev_root, 0);

    const dim3 cgrid(GN / 128, BB * TPB);   // (8, 16) = 128 blocks per chunk

    for (int c = 0; c < NC; ++c) {
        const int s0 = c * CS;

        // stage 1: input projection chunk (stream0)
        gemm_tf32_chunk<<<cgrid, 256>>>(x, w_in, xp, s0);
        cudaEventRecord(ev_g1[c], 0);

        // stage 2: scan chunk (s_scan) — waits on its xp chunk
        cudaStreamWaitEvent(s_scan, ev_g1[c], 0);
        rnn_scan_chunk<<<BB * HH, 32, 0, s_scan>>>(xp, h0, Wst, bias, yy, s0);
        cudaEventRecord(ev_sc[c], s_scan);

        // stage 3: output projection chunk (s_out) — waits on its y chunk
        cudaStreamWaitEvent(s_out, ev_sc[c], 0);
        gemm_tf32_chunk<<<cgrid, 256, 0, s_out>>>(yy, w_out, out, s0);
    }

    // join both side streams back into the capture stream
    cudaEventRecord(ev_done, s_out);
    cudaStreamWaitEvent(0, ev_done, 0);
    cudaStreamWaitEvent(0, ev_sc[NC - 1], 0);
}

// round 17
// speedup vs baseline: 2.3337x; 1.0313x over previous
#include <cuda_runtime.h>
#include <cstdint>
#include <cstddef>

// Problem constants
#define BB 4
#define SS 4096
#define HH 16
#define DD 64
#define GM 16384   // B*S
#define GN 1024    // H*D == OUT
#define GK 1024    // IN == H*D

#define NC 8            // pipeline chunks
#define CS (SS / NC)    // 512 steps per chunk
#define TPB (CS / 128)  // M-tiles per batch per chunk = 4

// Intermediate buffers (allocation-free rule: device globals)
__device__ float g_xp[(size_t)GM * GN];   // input projection  [B,S,H*D]
__device__ float g_y [(size_t)GM * GN];   // scan outputs      [B,S,H*D]
__device__ float g_h [BB * HH * DD];      // carried h-state between chunks

// ---------------------------------------------------------------------------
// tf32 helpers
// ---------------------------------------------------------------------------
__device__ __forceinline__ uint32_t f2tf32(float f) {
    uint32_t u;
    asm("cvt.rna.tf32.f32 %0, %1;" : "=r"(u) : "f"(f));
    return u;
}

__device__ __forceinline__ void mma_tf32(float c[4], const uint32_t a[4], const uint32_t b[2]) {
    asm volatile(
        "mma.sync.aligned.m16n8k8.row.col.f32.tf32.tf32.f32 "
        "{%0,%1,%2,%3}, {%4,%5,%6,%7}, {%8,%9}, {%0,%1,%2,%3};"
        : "+f"(c[0]), "+f"(c[1]), "+f"(c[2]), "+f"(c[3])
        : "r"(a[0]), "r"(a[1]), "r"(a[2]), "r"(a[3]), "r"(b[0]), "r"(b[1]));
}

// ---------------------------------------------------------------------------
// Chunked GEMM: processes M-rows {b*SS + s0 + tile*128 | b in [0,4), tile in
// [0,TPB)} of C[M,N] = A[M,K] * B[N,K]^T.  grid = (GN/128, BB*TPB).
// Inner structure identical to the R12 gemm (265us full / ~1 wave per chunk).
// ---------------------------------------------------------------------------
__global__ __launch_bounds__(256) void gemm_tf32_chunk(
    const float* __restrict__ A, const float* __restrict__ B, float* __restrict__ C,
    int s0)
{
    __shared__ uint4 As4[128 * 8];
    __shared__ uint4 Bs4[128 * 8];

    const int tid  = threadIdx.x;
    const int warp = tid >> 5;
    const int lane = tid & 31;
    const int wm   = warp >> 1;      // 0..3
    const int wn   = warp & 1;       // 0..1
    const int g    = lane >> 2;      // group 0..7
    const int t4   = lane & 3;       // thread-in-group
    const int lr   = tid >> 3;       // staging row 0..31
    const int lc4  = tid & 7;        // staging float4 col 0..7

    const int bty  = blockIdx.y;
    const int bm   = (bty >> 2) * SS + s0 + (bty & 3) * 128;  // TPB==4
    const int bn   = blockIdx.x * 128;

    const float4* Ag = reinterpret_cast<const float4*>(A) + (size_t)(bm + lr) * (GK / 4) + lc4;
    const float4* Bg = reinterpret_cast<const float4*>(B) + (size_t)(bn + lr) * (GK / 4) + lc4;
    const int sw = lc4 ^ (lr & 7);

    float acc[2][8][4];
#pragma unroll
    for (int mi = 0; mi < 2; ++mi)
#pragma unroll
        for (int ni = 0; ni < 8; ++ni)
#pragma unroll
            for (int r = 0; r < 4; ++r) acc[mi][ni][r] = 0.f;

    float4 pa[4], pb[4];
#pragma unroll
    for (int i = 0; i < 4; ++i) {
        pa[i] = Ag[(size_t)i * 32 * (GK / 4)];
        pb[i] = Bg[(size_t)i * 32 * (GK / 4)];
    }

    const uint32_t* As = reinterpret_cast<const uint32_t*>(As4);
    const uint32_t* Bs = reinterpret_cast<const uint32_t*>(Bs4);
    const uint32_t* Abase = As + (wm * 32 + g) * 32 + t4;
    const uint32_t* Bbase = Bs + (wn * 64 + g) * 32 + t4;

    for (int kt = 0; kt < GK / 32; ++kt) {
        __syncthreads();
#pragma unroll
        for (int i = 0; i < 4; ++i) {
            As4[(lr + 32 * i) * 8 + sw] =
                make_uint4(f2tf32(pa[i].x), f2tf32(pa[i].y), f2tf32(pa[i].z), f2tf32(pa[i].w));
            Bs4[(lr + 32 * i) * 8 + sw] =
                make_uint4(f2tf32(pb[i].x), f2tf32(pb[i].y), f2tf32(pb[i].z), f2tf32(pb[i].w));
        }
        __syncthreads();

        if (kt + 1 < GK / 32) {
#pragma unroll
            for (int i = 0; i < 4; ++i) {
                pa[i] = Ag[(size_t)(kt + 1) * 8 + (size_t)i * 32 * (GK / 4)];
                pb[i] = Bg[(size_t)(kt + 1) * 8 + (size_t)i * 32 * (GK / 4)];
            }
        }

#pragma unroll
        for (int j = 0; j < 4; ++j) {
            const int x0 = ((2 * j) ^ g) * 4;
            uint32_t af[2][4];
#pragma unroll
            for (int mi = 0; mi < 2; ++mi) {
                const uint32_t* p = Abase + mi * 16 * 32;
                af[mi][0] = p[x0];
                af[mi][1] = p[8 * 32 + x0];
                af[mi][2] = p[x0 ^ 4];
                af[mi][3] = p[8 * 32 + (x0 ^ 4)];
            }
#pragma unroll
            for (int ni = 0; ni < 8; ++ni) {
                const uint32_t* p = Bbase + ni * 8 * 32;
                uint32_t bf[2] = { p[x0], p[x0 ^ 4] };
                mma_tf32(acc[0][ni], af[0], bf);
                mma_tf32(acc[1][ni], af[1], bf);
            }
        }
    }

#pragma unroll
    for (int mi = 0; mi < 2; ++mi) {
        const int row = bm + wm * 32 + mi * 16 + g;
#pragma unroll
        for (int ni = 0; ni < 8; ++ni) {
            const int col = bn + wn * 64 + ni * 8 + t4 * 2;
            *reinterpret_cast<float2*>(C + (size_t)row * GN + col) =
                make_float2(acc[mi][ni][0], acc[mi][ni][1]);
            *reinterpret_cast<float2*>(C + (size_t)(row + 8) * GN + col) =
                make_float2(acc[mi][ni][2], acc[mi][ni][3]);
        }
    }
}

// ---------------------------------------------------------------------------
// packed f32x2 helpers (sm_103a FFMA2 — only reachable via PTX)
// ---------------------------------------------------------------------------
__device__ __forceinline__ void ffma2(uint64_t& c, uint64_t a, uint64_t b) {
    asm("fma.rn.f32x2 %0, %1, %2, %0;" : "+l"(c) : "l"(a), "l"(b));
}
__device__ __forceinline__ void fadd2(uint64_t& c, uint64_t a) {
    asm("add.rn.f32x2 %0, %0, %1;" : "+l"(c) : "l"(a));
}
__device__ __forceinline__ float2 unpk(uint64_t v) {
    float2 r;
    asm("mov.b64 {%0,%1}, %2;" : "=f"(r.x), "=f"(r.y) : "l"(v));
    return r;
}

// fast tanh: 1 - 2/(exp(2z)+1).  ~45cyc, correct saturation, ~1e-7 error.
__device__ __forceinline__ float fast_tanh(float z) {
    float ez = __expf(z + z);
    return 1.0f - __fdividef(2.0f, ez + 1.0f);
}

// ---------------------------------------------------------------------------
// Warp-synchronous scan CHUNK: steps [s0, s0+CS).  Identical inner loop to
// the best (R14) scan — one warp per (b,h), no block barriers.  h-state
// carried across chunk launches in g_h (same stream -> ordered).
// ---------------------------------------------------------------------------
__global__ void __launch_bounds__(32) rnn_scan_chunk(
    const float* __restrict__ xp, const float* __restrict__ h0,
    const float* __restrict__ Wst, const float* __restrict__ bias,
    float* __restrict__ y, int s0)
{
    const int b  = blockIdx.x >> 4;
    const int h  = blockIdx.x & 15;
    const int t  = threadIdx.x;
    const int e0 = 2 * t;

    __shared__ __align__(16) float hs[2][64];

    // weight rows e0, e0+1 packed as f32x2 k-pairs
    uint64_t w0[32], w1[32];
    {
        const uint64_t* p0 = reinterpret_cast<const uint64_t*>(
            Wst + ((size_t)(h * 64 + e0)) * 64);
        const uint64_t* p1 = p0 + 32;
#pragma unroll
        for (int k = 0; k < 32; ++k) { w0[k] = p0[k]; w1[k] = p1[k]; }
    }
    const float2 be = *reinterpret_cast<const float2*>(bias + h * 64 + e0);

    // chunk-initial state: h0 for the first chunk, carried g_h otherwise
    const float* hsrc = (s0 == 0) ? (h0 + (size_t)(b * HH + h) * 64)
                                  : (g_h + (size_t)(b * HH + h) * 64);
    reinterpret_cast<float2*>(hs[0])[t] =
        reinterpret_cast<const float2*>(hsrc)[t];

    const float2* xb2 = reinterpret_cast<const float2*>(
        xp + (size_t)b * SS * 1024 + h * 64) + t;     // step stride = 512 float2
    float2* yb2 = reinterpret_cast<float2*>(
        y + (size_t)b * SS * 1024 + h * 64) + t;

    // depth-8 prefetch ring
    float2 xr[8];
#pragma unroll
    for (int i = 0; i < 8; ++i) xr[i] = xb2[(size_t)(s0 + i) * 512];

    __syncwarp();

    int cur = 0;
    for (int s = s0; s < s0 + CS; s += 8) {
#pragma unroll
        for (int i = 0; i < 8; ++i) {
            const int st = s + i;

            float2 xn = make_float2(0.f, 0.f);
            if (st + 8 < SS) xn = xb2[(size_t)(st + 8) * 512];

            const ulonglong2* hv = reinterpret_cast<const ulonglong2*>(hs[cur]);
            uint64_t a0[4] = {0, 0, 0, 0}, a1[4] = {0, 0, 0, 0};
#pragma unroll
            for (int k = 0; k < 16; ++k) {
                ulonglong2 q = hv[k];
                ffma2(a0[(2 * k) & 3],     w0[2 * k],     q.x);
                ffma2(a0[(2 * k + 1) & 3], w0[2 * k + 1], q.y);
                ffma2(a1[(2 * k) & 3],     w1[2 * k],     q.x);
                ffma2(a1[(2 * k + 1) & 3], w1[2 * k + 1], q.y);
            }
            fadd2(a0[0], a0[1]); fadd2(a0[2], a0[3]); fadd2(a0[0], a0[2]);
            fadd2(a1[0], a1[1]); fadd2(a1[2], a1[3]); fadd2(a1[0], a1[2]);
            float2 v0 = unpk(a0[0]);
            float2 v1 = unpk(a1[0]);

            const float hn0 = fast_tanh((v0.x + v0.y) + be.x + xr[i].x);
            const float hn1 = fast_tanh((v1.x + v1.y) + be.y + xr[i].y);
            const float2 hn = make_float2(hn0, hn1);

            yb2[(size_t)st * 512] = hn;
            *reinterpret_cast<float2*>(&hs[cur ^ 1][e0]) = hn;
            __syncwarp();
            cur ^= 1;

            xr[i] = xn;
        }
    }

    // persist chunk-final state
    reinterpret_cast<float2*>(g_h + (size_t)(b * HH + h) * 64)[t] =
        reinterpret_cast<const float2*>(hs[cur])[t];
}

// ---------------------------------------------------------------------------
// Launch: 3-stage chunked pipeline across 3 streams (fork/join via events —
// capture-legal).  GEMM1 chunks feed the scan; scan chunks feed GEMM2.
// Streams/events created lazily on the first (non-captured) call.
// ---------------------------------------------------------------------------
extern "C" void kernel_launch(void* const* d_in, const int* in_sizes, int n_in,
                              void* d_out, int out_size)
{
    const float* x     = (const float*)d_in[0];  // [B,S,IN]
    const float* h0    = (const float*)d_in[1];  // [B,H,D]
    const float* w_in  = (const float*)d_in[2];  // [H*D, IN]
    const float* Wst   = (const float*)d_in[3];  // [H,D,D]
    const float* bias  = (const float*)d_in[4];  // [H,D]
    const float* w_out = (const float*)d_in[5];  // [OUT, H*D]
    float* out = (float*)d_out;                  // [B,S,OUT]

    float *xp = nullptr, *yy = nullptr;
    cudaGetSymbolAddress((void**)&xp, g_xp);
    cudaGetSymbolAddress((void**)&yy, g_y);

    static cudaStream_t s_scan = nullptr, s_out = nullptr;
    static cudaEvent_t  ev_root = nullptr, ev_done = nullptr;
    static cudaEvent_t  ev_g1[NC], ev_sc[NC];
    if (!s_scan) {
        cudaStreamCreateWithFlags(&s_scan, cudaStreamNonBlocking);
        cudaStreamCreateWithFlags(&s_out,  cudaStreamNonBlocking);
        cudaEventCreateWithFlags(&ev_root, cudaEventDisableTiming);
        cudaEventCreateWithFlags(&ev_done, cudaEventDisableTiming);
        for (int c = 0; c < NC; ++c) {
            cudaEventCreateWithFlags(&ev_g1[c], cudaEventDisableTiming);
            cudaEventCreateWithFlags(&ev_sc[c], cudaEventDisableTiming);
        }
    }

    // fork side streams off the capture (legacy) stream
    cudaEventRecord(ev_root, 0);
    cudaStreamWaitEvent(s_scan, ev_root, 0);
    cudaStreamWaitEvent(s_out,  ev_root, 0);

    const dim3 cgrid(GN / 128, BB * TPB);   // (8, 16) = 128 blocks per chunk

    for (int c = 0; c < NC; ++c) {
        const int s0 = c * CS;

        // stage 1: input projection chunk (stream0)
        gemm_tf32_chunk<<<cgrid, 256>>>(x, w_in, xp, s0);
        cudaEventRecord(ev_g1[c], 0);

        // stage 2: scan chunk (s_scan) — waits on its xp chunk
        cudaStreamWaitEvent(s_scan, ev_g1[c], 0);
        rnn_scan_chunk<<<BB * HH, 32, 0, s_scan>>>(xp, h0, Wst, bias, yy, s0);
        cudaEventRecord(ev_sc[c], s_scan);

        // stage 3: output projection chunk (s_out) — waits on its y chunk
        cudaStreamWaitEvent(s_out, ev_sc[c], 0);
        gemm_tf32_chunk<<<cgrid, 256, 0, s_out>>>(yy, w_out, out, s0);
    }

    // join both side streams back into the capture stream
    cudaEventRecord(ev_done, s_out);
    cudaStreamWaitEvent(0, ev_done, 0);
    cudaStreamWaitEvent(0, ev_sc[NC - 1], 0);
}